// round 6
// baseline (speedup 1.0000x reference)
#include <cuda_runtime.h>
#include <cuda_bf16.h>

namespace {

constexpr int NQ     = 12;
constexpr int DIM    = 4096;
constexpr int LAYERS = 8;
constexpr int FEAT   = 3072;
constexpr int NCLASS = 10;
constexpr int TPB    = 128;   // threads per CTA, one state per CTA
constexpr int AMPS   = 32;    // amplitudes per thread
constexpr int RS     = 33;    // smem row stride (floats), conflict-free

// Arrangement A: amplitude i = (t<<5) | r
//   bits 0-4 = r (register), bits 5-9 = lane, bits 10-11 = warp
// Arrangement B: amplitude i = (rp<<7) | t
//   bits 7-11 = rp (register), bits 0-6 = t
// Qubit q acts on bit p = 11 - q. Per-layer CNOT chain == Gray map
// j = i ^ (i>>1). Tan-form butterflies (2 FFMA each); all cos factors are
// folded into one global scalar applied at normalization.
//
// Per layer MIO: 2 shfl stages (bits 5,6) + transpose round trip + Gray
// scatter round trip = 64 shfl + 128 smem ops per thread, 128 threads
// (25% fewer lane-ops and ~35% fewer wavefronts than the 256x16 variant).

__global__ void __launch_bounds__(TPB, 6) qnn_kernel(
    const float* __restrict__ x,       // [B, 3072]
    const float* __restrict__ angles,  // [8, 12]
    const float* __restrict__ W,       // [10, 4096]
    const float* __restrict__ bias,    // [10]
    float* __restrict__ out)           // [B, 10]
{
    __shared__ float s_t[LAYERS][NQ];   // tan table [layer][bit pos]
    __shared__ float bufA[TPB * RS];    // transpose buffer (16896 B)
    __shared__ float bufB[TPB * RS];    // gray-scatter buffer
    __shared__ float s_prod[4];         // per-warp cos products
    __shared__ float s_norm[4];         // per-warp sum-of-squares
    __shared__ float sred[4 * NCLASS];  // epilogue partials

    const int t    = threadIdx.x;
    const int lane = t & 31;
    const int warp = t >> 5;
    const int bb   = blockIdx.x;

    // ---- trig: tan per gate; accumulate global cos product ----
    float cp = 1.0f;
    if (t < LAYERS * NQ) {
        const int l = t / NQ;
        const int q = t - l * NQ;
        const float a = angles[t];
        const int p = NQ - 1 - q;       // qubit q -> bit position p
        const float c = cosf(a);
        s_t[l][p] = sinf(a) / c;
        cp = c;
    }
    #pragma unroll
    for (int o = 16; o > 0; o >>= 1)
        cp *= __shfl_xor_sync(0xffffffffu, cp, o);
    if (lane == 0) s_prod[warp] = cp;

    // ---- load input row (pad 3072 -> 4096), arrangement A ----
    float v[AMPS];
    if (t < FEAT / AMPS) {   // t < 96
        const float4* x4 = reinterpret_cast<const float4*>(x)
                         + (size_t)bb * (FEAT / 4) + t * (AMPS / 4);
        #pragma unroll
        for (int i = 0; i < AMPS / 4; i++) {
            const float4 w4 = x4[i];
            v[4*i+0] = w4.x; v[4*i+1] = w4.y; v[4*i+2] = w4.z; v[4*i+3] = w4.w;
        }
    } else {
        #pragma unroll
        for (int r = 0; r < AMPS; r++) v[r] = 0.0f;
    }

    // ---- L2 norm, fold in cos product ----
    float ssq = 0.0f;
    #pragma unroll
    for (int r = 0; r < AMPS; r++) ssq = fmaf(v[r], v[r], ssq);
    #pragma unroll
    for (int o = 16; o > 0; o >>= 1) ssq += __shfl_xor_sync(0xffffffffu, ssq, o);
    if (lane == 0) s_norm[warp] = ssq;
    __syncthreads();   // publishes trig table, s_prod, s_norm
    {
        const float tot  = s_norm[0] + s_norm[1] + s_norm[2] + s_norm[3];
        const float ctot = s_prod[0] * s_prod[1] * s_prod[2] * s_prod[3];
        const float rn = rsqrtf(tot) * ctot;
        #pragma unroll
        for (int r = 0; r < AMPS; r++) v[r] *= rn;
    }

    const int g_t   = t ^ (t >> 1);           // 7-bit Gray of thread id
    const int baseA = t * RS;
    const int baseB = warp * RS + lane;       // + (rp*4)*RS per rp

    #pragma unroll 1
    for (int l = 0; l < LAYERS; l++) {
        // ---- gates on bits 0..4 (register butterflies, tan form) ----
        #pragma unroll
        for (int p = 0; p < 5; p++) {
            const float tg = s_t[l][p];
            const int m = 1 << p;
            #pragma unroll
            for (int lo = 0; lo < AMPS; lo += 2 * m)
                #pragma unroll
                for (int k = 0; k < m; k++) {
                    const int r0 = lo + k, r1 = r0 + m;
                    const float a0 = v[r0], a1 = v[r1];
                    v[r0] = fmaf(-tg, a1, a0);
                    v[r1] = fmaf( tg, a0, a1);
                }
        }

        // ---- gates on bits 5,6 via shfl_xor (lane bits 0,1) ----
        #pragma unroll
        for (int p = 5; p < 7; p++) {
            const float tg = s_t[l][p];
            const int mask = 1 << (p - 5);
            const float se = (lane & mask) ? tg : -tg;
            #pragma unroll
            for (int r = 0; r < AMPS; r++) {
                const float pr = __shfl_xor_sync(0xffffffffu, v[r], mask);
                v[r] = fmaf(se, pr, v[r]);
            }
        }

        // ---- transpose A -> B through bufA ----
        #pragma unroll
        for (int r = 0; r < AMPS; r++) bufA[baseA + r] = v[r];
        __syncthreads();
        #pragma unroll
        for (int rp = 0; rp < AMPS; rp++) v[rp] = bufA[baseB + (rp * 4) * RS];

        // ---- gates on bits 7..11 (register butterflies in B) ----
        #pragma unroll
        for (int p = 0; p < 5; p++) {
            const float tg = s_t[l][p + 7];
            const int m = 1 << p;
            #pragma unroll
            for (int lo = 0; lo < AMPS; lo += 2 * m)
                #pragma unroll
                for (int k = 0; k < m; k++) {
                    const int r0 = lo + k, r1 = r0 + m;
                    const float a0 = v[r0], a1 = v[r1];
                    v[r0] = fmaf(-tg, a1, a0);
                    v[r1] = fmaf( tg, a0, a1);
                }
        }

        // ---- Gray scatter B -> A through bufB: j = i ^ (i>>1) ----
        #pragma unroll
        for (int rp = 0; rp < AMPS; rp++) {
            const int j = ((rp << 7) ^ (rp << 6)) ^ g_t;
            bufB[(j >> 5) * RS + (j & 31)] = v[rp];
        }
        __syncthreads();
        #pragma unroll
        for (int r = 0; r < AMPS; r++) v[r] = bufB[baseA + r];
    }

    // ---- probabilities ----
    #pragma unroll
    for (int r = 0; r < AMPS; r++) v[r] = v[r] * v[r];

    // ---- readout: out[k] = sum_i probs[i] * W[k,i] + b[k] ----
    #pragma unroll 1
    for (int k = 0; k < NCLASS; k++) {
        const float4* w4 = reinterpret_cast<const float4*>(W + (size_t)k * DIM)
                         + t * (AMPS / 4);
        float a = 0.0f;
        #pragma unroll
        for (int i = 0; i < AMPS / 4; i++) {
            const float4 w = w4[i];
            a = fmaf(v[4*i+0], w.x, a);
            a = fmaf(v[4*i+1], w.y, a);
            a = fmaf(v[4*i+2], w.z, a);
            a = fmaf(v[4*i+3], w.w, a);
        }
        #pragma unroll
        for (int o = 16; o > 0; o >>= 1) a += __shfl_xor_sync(0xffffffffu, a, o);
        if (lane == 0) sred[k * 4 + warp] = a;
    }
    __syncthreads();
    if (t < NCLASS) {
        out[bb * NCLASS + t] = sred[t * 4 + 0] + sred[t * 4 + 1]
                             + sred[t * 4 + 2] + sred[t * 4 + 3] + bias[t];
    }
}

} // namespace

extern "C" void kernel_launch(void* const* d_in, const int* in_sizes, int n_in,
                              void* d_out, int out_size) {
    const float* x      = (const float*)d_in[0];
    const float* angles = (const float*)d_in[1];
    const float* W      = (const float*)d_in[2];
    const float* bias   = (const float*)d_in[3];
    const int batch = in_sizes[0] / FEAT;   // 2048
    qnn_kernel<<<batch, TPB>>>(x, angles, W, bias, (float*)d_out);
}

// round 7
// speedup vs baseline: 1.4488x; 1.4488x over previous
#include <cuda_runtime.h>
#include <cuda_bf16.h>

namespace {

constexpr int NQ     = 12;
constexpr int DIM    = 4096;
constexpr int LAYERS = 8;
constexpr int FEAT   = 3072;
constexpr int NCLASS = 10;
constexpr int TPB    = 256;   // threads per CTA; CTA simulates TWO states
constexpr int AMPS   = 16;    // amplitudes per thread per state
constexpr int RS     = 17;    // smem row stride in float2 units

// Arrangement A: amplitude i = (t<<4) | r   (bits 0-3 register-local,
//   bits 4-8 lane, bits 9-11 warp)
// Arrangement B: amplitude i = (rp<<8) | t  (bits 8-11 register-local)
// Qubit q acts on bit p = 11 - q. CNOT chain == Gray map j = i ^ (i>>1).
// Tan-form butterflies; cos product folded into normalization.
// Two batch rows per CTA, carried as float2 through shared exchanges
// (all 64-bit smem patterns verified exactly 2-way conflict = full BW).

__global__ void __launch_bounds__(TPB, 4) qnn_kernel(
    const float* __restrict__ x,       // [B, 3072]
    const float* __restrict__ angles,  // [8, 12]
    const float* __restrict__ W,       // [10, 4096]
    const float* __restrict__ bias,    // [10]
    float* __restrict__ out)           // [B, 10]
{
    __shared__ float  s_t[LAYERS][NQ];     // tan table [layer][bit pos]
    __shared__ float2 buf[TPB * RS];       // exchange buffer (34816 B)
    __shared__ float  s_prod[8];           // per-warp cos products
    __shared__ float2 s_norm[8];           // per-warp sum-of-squares (2 states)
    __shared__ float2 sred[8 * NCLASS];    // epilogue partials

    const int t    = threadIdx.x;
    const int lane = t & 31;
    const int warp = t >> 5;
    const int bb   = blockIdx.x;

    // ---- trig: tan per gate; accumulate global cos product ----
    float cp = 1.0f;
    if (t < LAYERS * NQ) {
        const int l = t / NQ;
        const int q = t - l * NQ;
        const float a = angles[t];
        const int p = NQ - 1 - q;           // qubit q -> bit position p
        const float c = cosf(a);
        s_t[l][p] = sinf(a) / c;
        cp = c;
    }
    #pragma unroll
    for (int o = 16; o > 0; o >>= 1)
        cp *= __shfl_xor_sync(0xffffffffu, cp, o);
    if (lane == 0) s_prod[warp] = cp;

    // ---- load two input rows (pad 3072 -> 4096), arrangement A ----
    float v0[AMPS], v1[AMPS];
    if (t < FEAT / AMPS) {   // t < 192
        const float4* x0 = reinterpret_cast<const float4*>(x)
                         + (size_t)(2 * bb)     * (FEAT / 4) + t * (AMPS / 4);
        const float4* x1 = reinterpret_cast<const float4*>(x)
                         + (size_t)(2 * bb + 1) * (FEAT / 4) + t * (AMPS / 4);
        #pragma unroll
        for (int i = 0; i < AMPS / 4; i++) {
            const float4 a4 = x0[i];
            v0[4*i+0] = a4.x; v0[4*i+1] = a4.y; v0[4*i+2] = a4.z; v0[4*i+3] = a4.w;
            const float4 b4 = x1[i];
            v1[4*i+0] = b4.x; v1[4*i+1] = b4.y; v1[4*i+2] = b4.z; v1[4*i+3] = b4.w;
        }
    } else {
        #pragma unroll
        for (int r = 0; r < AMPS; r++) { v0[r] = 0.0f; v1[r] = 0.0f; }
    }

    // ---- per-state L2 norm, fold in cos product ----
    float q0 = 0.0f, q1 = 0.0f;
    #pragma unroll
    for (int r = 0; r < AMPS; r++) {
        q0 = fmaf(v0[r], v0[r], q0);
        q1 = fmaf(v1[r], v1[r], q1);
    }
    #pragma unroll
    for (int o = 16; o > 0; o >>= 1) {
        q0 += __shfl_xor_sync(0xffffffffu, q0, o);
        q1 += __shfl_xor_sync(0xffffffffu, q1, o);
    }
    if (lane == 0) s_norm[warp] = make_float2(q0, q1);
    __syncthreads();   // publishes trig table, s_prod, s_norm
    {
        float t0 = 0.0f, t1 = 0.0f, ctot = 1.0f;
        #pragma unroll
        for (int w = 0; w < 8; w++) {
            t0 += s_norm[w].x; t1 += s_norm[w].y; ctot *= s_prod[w];
        }
        const float rn0 = rsqrtf(t0) * ctot;
        const float rn1 = rsqrtf(t1) * ctot;
        #pragma unroll
        for (int r = 0; r < AMPS; r++) { v0[r] *= rn0; v1[r] *= rn1; }
    }

    const int g_t   = t ^ (t >> 1);                 // 8-bit Gray of thread id
    const int baseA = t * RS;
    const int baseB = (t >> 4) * RS + (t & 15);     // + (rp<<4)*RS per rp

    #pragma unroll 1
    for (int l = 0; l < LAYERS; l++) {
        // ---- gates on bits 0..3 (register butterflies, both states) ----
        #pragma unroll
        for (int p = 0; p < 4; p++) {
            const float tg = s_t[l][p];
            const int m = 1 << p;
            #pragma unroll
            for (int lo = 0; lo < AMPS; lo += 2 * m)
                #pragma unroll
                for (int k = 0; k < m; k++) {
                    const int r0 = lo + k, r1 = r0 + m;
                    float a0 = v0[r0], a1 = v0[r1];
                    v0[r0] = fmaf(-tg, a1, a0);
                    v0[r1] = fmaf( tg, a0, a1);
                    a0 = v1[r0]; a1 = v1[r1];
                    v1[r0] = fmaf(-tg, a1, a0);
                    v1[r1] = fmaf( tg, a0, a1);
                }
        }

        // ---- gates on bits 4..7 via shfl_xor (lane bits 0..3) ----
        #pragma unroll
        for (int p = 4; p < 8; p++) {
            const float tg = s_t[l][p];
            const int mask = 1 << (p - 4);
            const float se = (lane & mask) ? tg : -tg;
            #pragma unroll
            for (int r = 0; r < AMPS; r++) {
                const float p0 = __shfl_xor_sync(0xffffffffu, v0[r], mask);
                const float p1 = __shfl_xor_sync(0xffffffffu, v1[r], mask);
                v0[r] = fmaf(se, p0, v0[r]);
                v1[r] = fmaf(se, p1, v1[r]);
            }
        }

        // ---- transpose A -> B ----
        #pragma unroll
        for (int r = 0; r < AMPS; r++)
            buf[baseA + r] = make_float2(v0[r], v1[r]);
        __syncthreads();
        #pragma unroll
        for (int rp = 0; rp < AMPS; rp++) {
            const float2 w2 = buf[baseB + (rp << 4) * RS];
            v0[rp] = w2.x; v1[rp] = w2.y;
        }

        // ---- gates on bits 8..11 (register butterflies in B) ----
        #pragma unroll
        for (int p = 0; p < 4; p++) {
            const float tg = s_t[l][p + 8];
            const int m = 1 << p;
            #pragma unroll
            for (int lo = 0; lo < AMPS; lo += 2 * m)
                #pragma unroll
                for (int k = 0; k < m; k++) {
                    const int r0 = lo + k, r1 = r0 + m;
                    float a0 = v0[r0], a1 = v0[r1];
                    v0[r0] = fmaf(-tg, a1, a0);
                    v0[r1] = fmaf( tg, a0, a1);
                    a0 = v1[r0]; a1 = v1[r1];
                    v1[r0] = fmaf(-tg, a1, a0);
                    v1[r1] = fmaf( tg, a0, a1);
                }
        }

        __syncthreads();   // WAR: transpose reads complete before scatter

        // ---- Gray scatter B -> A: j = i ^ (i>>1), i = (rp<<8)|t ----
        #pragma unroll
        for (int rp = 0; rp < AMPS; rp++) {
            const int j = ((rp << 8) ^ (rp << 7)) ^ g_t;
            buf[(j >> 4) * RS + (j & 15)] = make_float2(v0[rp], v1[rp]);
        }
        __syncthreads();
        #pragma unroll
        for (int r = 0; r < AMPS; r++) {
            const float2 w2 = buf[baseA + r];    // own row: next write is own row too
            v0[r] = w2.x; v1[r] = w2.y;
        }
    }

    // ---- probabilities ----
    #pragma unroll
    for (int r = 0; r < AMPS; r++) { v0[r] *= v0[r]; v1[r] *= v1[r]; }

    // ---- readout: out[k] = sum_i probs[i] * W[k,i] + b[k], both states ----
    #pragma unroll 1
    for (int k = 0; k < NCLASS; k++) {
        const float4* w4 = reinterpret_cast<const float4*>(W + (size_t)k * DIM)
                         + t * (AMPS / 4);
        float a0 = 0.0f, a1 = 0.0f;
        #pragma unroll
        for (int i = 0; i < AMPS / 4; i++) {
            const float4 w = w4[i];
            a0 = fmaf(v0[4*i+0], w.x, a0);  a1 = fmaf(v1[4*i+0], w.x, a1);
            a0 = fmaf(v0[4*i+1], w.y, a0);  a1 = fmaf(v1[4*i+1], w.y, a1);
            a0 = fmaf(v0[4*i+2], w.z, a0);  a1 = fmaf(v1[4*i+2], w.z, a1);
            a0 = fmaf(v0[4*i+3], w.w, a0);  a1 = fmaf(v1[4*i+3], w.w, a1);
        }
        #pragma unroll
        for (int o = 16; o > 0; o >>= 1) {
            a0 += __shfl_xor_sync(0xffffffffu, a0, o);
            a1 += __shfl_xor_sync(0xffffffffu, a1, o);
        }
        if (lane == 0) sred[k * 8 + warp] = make_float2(a0, a1);
    }
    __syncthreads();
    if (t < NCLASS) {
        float a0 = bias[t], a1 = a0;
        #pragma unroll
        for (int w = 0; w < 8; w++) {
            a0 += sred[t * 8 + w].x;
            a1 += sred[t * 8 + w].y;
        }
        out[(size_t)(2 * bb)     * NCLASS + t] = a0;
        out[(size_t)(2 * bb + 1) * NCLASS + t] = a1;
    }
}

} // namespace

extern "C" void kernel_launch(void* const* d_in, const int* in_sizes, int n_in,
                              void* d_out, int out_size) {
    const float* x      = (const float*)d_in[0];
    const float* angles = (const float*)d_in[1];
    const float* W      = (const float*)d_in[2];
    const float* bias   = (const float*)d_in[3];
    const int batch = in_sizes[0] / FEAT;   // 2048
    qnn_kernel<<<batch / 2, TPB>>>(x, angles, W, bias, (float*)d_out);
}